// round 13
// baseline (speedup 1.0000x reference)
#include <cuda_runtime.h>
#include <cuda_bf16.h>
#include <cstdint>

#define NPTS 8192
#define CH   256
#define KNB  16

#define GRID   8
#define NCELLS 512
#define CELLSZ 12.5f
#define INVCELL 0.08f
#define KNN_TAU 120.0f

// scratch (device globals: no allocation allowed)
__device__ int   g_idx[NPTS * KNB];
__device__ float g_theta[NPTS * CH];
__device__ float g_phi[NPTS * CH];
__device__ float g_gf[NPTS * CH];
__device__ uint32_t g_w2pack[4 * 8192];        // attn W2, bf16x2 smem image
__device__ uint32_t g_ypack[NPTS * 256];       // y, (hi,lo) bf16 words
__device__ uint32_t g_wpack[4 * 2 * 4 * 512 * 32];  // weights [wsel][plane][nc][512][32]

__device__ int2   g_cellSC[NCELLS];    // (start, count)
__device__ int    g_cellCnt[NCELLS];
__device__ int    g_cellOffs[NCELLS];
__device__ float4 g_spts[NPTS];
__device__ int    g_sidx[NPTS];
__device__ int    g_pcell[NPTS];

__device__ __forceinline__ bool pair_less(float d1, int i1, float d2, int i2) {
    return d1 < d2 || (d1 == d2 && i1 < i2);
}

__device__ __forceinline__ int cell_of(float x) {
    int c = (int)(x * INVCELL);
    return c < 0 ? 0 : (c > GRID - 1 ? GRID - 1 : c);
}

__device__ __forceinline__ uint32_t smem_u32(const void* p) {
    uint32_t a;
    asm("{ .reg .u64 t; cvta.to.shared.u64 t, %1; cvt.u32.u64 %0, t; }" : "=r"(a) : "l"(p));
    return a;
}

// fp32 -> (bf16 hi | bf16 lo << 16)
__device__ __forceinline__ uint32_t splitw(float v) {
    __nv_bfloat16 h = __float2bfloat16(v);
    float l = v - __bfloat162float(h);
    __nv_bfloat16 lo = __float2bfloat16(l);
    return (uint32_t)__bfloat16_as_ushort(h) | ((uint32_t)__bfloat16_as_ushort(lo) << 16);
}

// ---------------------------------------------------------------------------
// Grid build (g_cellCnt zeroed by grid_prefix after use)
// ---------------------------------------------------------------------------
__global__ void grid_count_kernel(const float* __restrict__ coords) {
    int i = blockIdx.x * 256 + threadIdx.x;
    float x = coords[3*i+0], y = coords[3*i+1], z = coords[3*i+2];
    int c = (cell_of(z) * GRID + cell_of(y)) * GRID + cell_of(x);
    g_pcell[i] = c;
    atomicAdd(&g_cellCnt[c], 1);
}

__global__ void grid_prefix_kernel() {
    __shared__ int tmp[NCELLS];
    int t = threadIdx.x;
    int v = g_cellCnt[t];
    tmp[t] = v;
    __syncthreads();
    for (int off = 1; off < NCELLS; off <<= 1) {
        int a = (t >= off) ? tmp[t - off] : 0;
        __syncthreads();
        tmp[t] += a;
        __syncthreads();
    }
    int excl = tmp[t] - v;
    g_cellSC[t]   = make_int2(excl, v);
    g_cellOffs[t] = excl;
    g_cellCnt[t]  = 0;
}

__global__ void grid_scatter_kernel(const float* __restrict__ coords) {
    int i = blockIdx.x * 256 + threadIdx.x;
    float x = coords[3*i+0], y = coords[3*i+1], z = coords[3*i+2];
    int c = g_pcell[i];
    int pos = atomicAdd(&g_cellOffs[c], 1);
    g_spts[pos] = make_float4(x, y, z, x*x + y*y + z*z);
    g_sidx[pos] = i;
}

// fused weight prepack: attn W2 image + two-plane gemm weights
__global__ void prep_w_kernel(const float* __restrict__ pw2,
                              const float* __restrict__ w0, const float* __restrict__ w1,
                              const float* __restrict__ w2, const float* __restrict__ w3)
{
    int idx = blockIdx.x * 256 + threadIdx.x;
    if (idx < 32768) {
        int nc = idx >> 13, rem = idx & 8191;
        int q = rem & 31, k = rem >> 5;
        const float* p = pw2 + k * CH + nc * 64 + 2 * q;
        ((__nv_bfloat162*)g_w2pack)[idx] = __floats2bfloat162_rn(p[0], p[1]);
        return;
    }
    int i2 = idx - 32768;
    int wsel  = i2 >> 17;
    int plane = (i2 >> 16) & 1;
    int nc    = (i2 >> 14) & 3;
    int row   = (i2 >> 5) & 511;
    int wq    = i2 & 31;
    int k = row >> 1;
    int n = nc * 64 + wq * 2;
    const float* W = wsel == 0 ? w0 : (wsel == 1 ? w1 : (wsel == 2 ? w2 : w3));
    float v0 = W[k * 256 + n], v1 = W[k * 256 + n + 1];
    uint16_t a, b;
    if (plane == 0) {
        a = __bfloat16_as_ushort(__float2bfloat16(v0));
        b = __bfloat16_as_ushort(__float2bfloat16(v1));
    } else {
        a = __bfloat16_as_ushort(__float2bfloat16(v0 - __bfloat162float(__float2bfloat16(v0))));
        b = __bfloat16_as_ushort(__float2bfloat16(v1 - __bfloat162float(__float2bfloat16(v1))));
    }
    g_wpack[i2] = (uint32_t)a | ((uint32_t)b << 16);
}

// ---------------------------------------------------------------------------
// Grid KNN v3: 9 contiguous ranges per (z,y) slab + tau prefilter with exact
// fallback. (4th launch -> profiled)
// ---------------------------------------------------------------------------
__global__ __launch_bounds__(256) void knn_grid_kernel(const float* __restrict__ coords) {
    int tid  = threadIdx.x;
    int lane = tid & 31;
    int q    = blockIdx.x * 8 + (tid >> 5);

    float qx = coords[3*q+0], qy = coords[3*q+1], qz = coords[3*q+2];
    float qsq = qx*qx + qy*qy + qz*qz;
    int cx = cell_of(qx), cy = cell_of(qy), cz = cell_of(qz);

    for (int R = 1; R <= GRID; ++R) {
        int x0 = max(cx - R, 0), x1 = min(cx + R, GRID - 1);
        int y0 = max(cy - R, 0), y1 = min(cy + R, GRID - 1);
        int z0 = max(cz - R, 0), z1 = min(cz + R, GRID - 1);

        float bd[KNB]; int bi[KNB];
        float tau = KNN_TAU;

        for (int pass = 0; pass < 2; ++pass) {
#pragma unroll
            for (int t = 0; t < KNB; ++t) { bd[t] = 3.4e38f; bi[t] = 0x7fffffff; }
            int cnt = 0;

            for (int zz = z0; zz <= z1; ++zz)
            for (int yy = y0; yy <= y1; ++yy) {
                int base = (zz * GRID + yy) * GRID;
                int2 sA = g_cellSC[base + x0];
                int2 sB = g_cellSC[base + x1];
                int st = sA.x, en = sB.x + sB.y;   // contiguous x-run
                for (int i = st + lane; i < en; i += 32) {
                    float4 p = g_spts[i];
                    float d = qsq + p.w - 2.0f * (qx*p.x + qy*p.y + qz*p.z);
                    if (d < tau) {
                        ++cnt;
                        int j = g_sidx[i];
                        if (pair_less(d, j, bd[KNB-1], bi[KNB-1])) {
                            float cd = d; int ci = j;
#pragma unroll
                            for (int t = 0; t < KNB; ++t) {
                                bool sw = pair_less(cd, ci, bd[t], bi[t]);
                                float td = sw ? bd[t] : cd; int ti = sw ? bi[t] : ci;
                                bd[t] = sw ? cd : bd[t];   bi[t] = sw ? ci : bi[t];
                                cd = td; ci = ti;
                            }
                        }
                    }
                }
            }

            int total = cnt;
#pragma unroll
            for (int off = 16; off; off >>= 1)
                total += __shfl_xor_sync(0xffffffffu, total, off);
            if (total >= KNB) break;    // tau-filtered set provably contains top-16
            tau = 3.4e38f;              // rare: boundary-clipped query, rescan all
        }

        // warp merge: 16 rounds of min-reduce over per-lane sorted heads
        float hd = bd[0]; int hi = bi[0];
        float r16 = 3.4e38f;
        for (int k = 0; k < KNB; ++k) {
            float md = hd; int mi = hi;
#pragma unroll
            for (int off = 16; off; off >>= 1) {
                float od = __shfl_xor_sync(0xffffffffu, md, off);
                int   oi = __shfl_xor_sync(0xffffffffu, mi, off);
                if (pair_less(od, oi, md, mi)) { md = od; mi = oi; }
            }
            if (lane == 0) g_idx[q * KNB + k] = mi;
            r16 = md;
            if (hd == md && hi == mi) {
#pragma unroll
                for (int t = 0; t < KNB-1; ++t) { bd[t] = bd[t+1]; bi[t] = bi[t+1]; }
                bd[KNB-1] = 3.4e38f; bi[KNB-1] = 0x7fffffff;
                hd = bd[0]; hi = bi[0];
            }
        }

        float bmin = 1e30f;
        if (x0 > 0)        bmin = fminf(bmin, qx - (float)x0 * CELLSZ);
        if (x1 < GRID - 1) bmin = fminf(bmin, (float)(x1 + 1) * CELLSZ - qx);
        if (y0 > 0)        bmin = fminf(bmin, qy - (float)y0 * CELLSZ);
        if (y1 < GRID - 1) bmin = fminf(bmin, (float)(y1 + 1) * CELLSZ - qy);
        if (z0 > 0)        bmin = fminf(bmin, qz - (float)z0 * CELLSZ);
        if (z1 < GRID - 1) bmin = fminf(bmin, (float)(z1 + 1) * CELLSZ - qz);
        if (r16 <= bmin * bmin - 0.5f) break;
    }
}

// ---------------------------------------------------------------------------
// Split-bf16 tensor GEMM. A either fp32 (split on the fly) or prepacked words.
// ---------------------------------------------------------------------------
#define GSTR 36   // words per smem row (72 bf16 = 144B)

__global__ __launch_bounds__(256) void gemmsp_kernel(
    const float* __restrict__ Af, const uint32_t* __restrict__ Ap,
    const uint32_t* __restrict__ Bp,
    const float* __restrict__ bias0, const float* __restrict__ bias1,
    const float* __restrict__ bias2,
    float* __restrict__ out0, float* __restrict__ out1, float* __restrict__ out2,
    const float* __restrict__ resid)
{
    __shared__ __align__(16) uint32_t As[128 * GSTR];
    __shared__ __align__(16) uint32_t Bs[64 * GSTR];

    const int tid = threadIdx.x, lane = tid & 31, w = tid >> 5;
    const int wm = w & 3, wn = w >> 2;
    const int m0 = blockIdx.y * 128;
    const int nc = blockIdx.x & 3;
    const int wsel = blockIdx.x >> 2;
    const float* bias = wsel == 0 ? bias0 : (wsel == 1 ? bias1 : bias2);
    float* outp = wsel == 0 ? out0 : (wsel == 1 ? out1 : out2);

    float acc[2][4][4];
#pragma unroll
    for (int t = 0; t < 2; ++t)
#pragma unroll
        for (int u = 0; u < 4; ++u)
#pragma unroll
            for (int i = 0; i < 4; ++i) acc[t][u][i] = 0.f;

    uint4 aR[4], bR[2];
    const int arow4 = tid >> 3, awq = (tid & 7) * 4;

#define LD_A(c) { \
    if (Af) { \
        _Pragma("unroll") \
        for (int u2 = 0; u2 < 4; ++u2) { \
            float4 f = *(const float4*)&Af[(size_t)(m0 + arow4 + u2 * 32) * 256 + (c) * 32 + awq]; \
            aR[u2].x = splitw(f.x); aR[u2].y = splitw(f.y); \
            aR[u2].z = splitw(f.z); aR[u2].w = splitw(f.w); \
        } \
    } else { \
        _Pragma("unroll") \
        for (int u2 = 0; u2 < 4; ++u2) \
            aR[u2] = *(const uint4*)&Ap[(size_t)(m0 + arow4 + u2 * 32) * 256 + (c) * 32 + awq]; \
    } }
#define LD_B(c, pl) { \
    _Pragma("unroll") \
    for (int u2 = 0; u2 < 2; ++u2) \
        bR[u2] = *(const uint4*)&Bp[((((size_t)wsel * 2 + (pl)) * 4 + nc) * 512 + (size_t)(c) * 64 + arow4 + u2 * 32) * 32 + awq]; }

    LD_A(0); LD_B(0, 0);

    const uint32_t smA = smem_u32(As), smB = smem_u32(Bs);
    const uint32_t aBase = smA + (uint32_t)((wm * 32 + (lane & 15)) * 144 + (lane >> 4) * 16);
    const uint32_t bBase = smB + (uint32_t)((lane & 15) * 144 + wn * 64);

    for (int s = 0; s < 16; ++s) {
        const int plane = s & 1;
        __syncthreads();
        if (plane == 0) {
#pragma unroll
            for (int u2 = 0; u2 < 4; ++u2)
                *(uint4*)&As[(arow4 + u2 * 32) * GSTR + awq] = aR[u2];
        }
#pragma unroll
        for (int u2 = 0; u2 < 2; ++u2)
            *(uint4*)&Bs[(arow4 + u2 * 32) * GSTR + awq] = bR[u2];
        __syncthreads();

        if (s < 15) {
            const int c2 = (s + 1) >> 1, p2 = (s + 1) & 1;
            if (p2 == 0) LD_A(c2);
            LD_B(c2, p2);
        }

#pragma unroll
        for (int ks = 0; ks < 4; ++ks) {
            uint32_t a[2][4];
#pragma unroll
            for (int t = 0; t < 2; ++t)
                asm volatile("ldmatrix.sync.aligned.m8n8.x4.shared.b16 {%0,%1,%2,%3}, [%4];"
                             : "=r"(a[t][0]), "=r"(a[t][1]), "=r"(a[t][2]), "=r"(a[t][3])
                             : "r"(aBase + (uint32_t)(t * 16 * 144 + ks * 32)));
#pragma unroll
            for (int u = 0; u < 4; ++u) {
                uint32_t b0, b1;
                asm volatile("ldmatrix.sync.aligned.m8n8.x2.trans.shared.b16 {%0,%1}, [%2];"
                             : "=r"(b0), "=r"(b1)
                             : "r"(bBase + (uint32_t)(ks * 16 * 144 + u * 16)));
#pragma unroll
                for (int t = 0; t < 2; ++t)
                    asm volatile("mma.sync.aligned.m16n8k16.row.col.f32.bf16.bf16.f32 "
                                 "{%0,%1,%2,%3}, {%4,%5,%6,%7}, {%8,%9}, {%0,%1,%2,%3};"
                                 : "+f"(acc[t][u][0]), "+f"(acc[t][u][1]),
                                   "+f"(acc[t][u][2]), "+f"(acc[t][u][3])
                                 : "r"(a[t][0]), "r"(a[t][1]), "r"(a[t][2]), "r"(a[t][3]),
                                   "r"(b0), "r"(b1));
            }
        }
    }

#pragma unroll
    for (int t = 0; t < 2; ++t) {
        int r0 = m0 + wm * 32 + t * 16 + (lane >> 2);
#pragma unroll
        for (int u = 0; u < 4; ++u) {
            int nb = nc * 64 + wn * 32 + u * 8 + 2 * (lane & 3);
            float2 b = *(const float2*)&bias[nb];
            float2 o0 = make_float2(acc[t][u][0] + b.x, acc[t][u][1] + b.y);
            float2 o1 = make_float2(acc[t][u][2] + b.x, acc[t][u][3] + b.y);
            if (resid) {
                float2 ra = *(const float2*)&resid[(size_t)r0 * 256 + nb];
                float2 rb = *(const float2*)&resid[(size_t)(r0 + 8) * 256 + nb];
                o0.x += ra.x; o0.y += ra.y; o1.x += rb.x; o1.y += rb.y;
            }
            *(float2*)&outp[(size_t)r0 * 256 + nb]       = o0;
            *(float2*)&outp[(size_t)(r0 + 8) * 256 + nb] = o1;
        }
    }
}

// ===========================================================================
// Fused attention (HMMA), barrier-free: 8 points, 256 threads, 1 CTA/SM.
// ALL W2 chunks (147KB) + H (66KB) staged once; after one sync each warp
// runs its 4 chunk GEMM+epilogue loops independently (no barriers).
// ===========================================================================
#define OFF_JS   0
#define OFF_DC   512
#define OFF_W1   2048
#define OFF_H    6144
#define HSTR_B   528
#define OFF_W2   73728
#define WSTR_B   144
#define W2CHUNK  36864
#define ATTN_SMEM 221184

__global__ __launch_bounds__(256, 1) void attn_kernel(
    const float* __restrict__ coords,
    const float* __restrict__ pw1, const float* __restrict__ pb1,
    const float* __restrict__ pb2)
{
    extern __shared__ __align__(16) char sm[];
    int*    js  = (int*)(sm + OFF_JS);
    float*  dc0 = (float*)(sm + OFF_DC);
    float*  dc1 = dc0 + 128;
    float*  dc2 = dc0 + 256;
    float4* w1f = (float4*)(sm + OFF_W1);

    const int tid  = threadIdx.x;
    const int lane = tid & 31;
    const int wp   = tid >> 5;          // warp = point (0..7)
    const int n0   = blockIdx.x * 8;

    if (tid < 128) {
        int p = tid >> 4, k = tid & 15;
        int n = n0 + p;
        int j = g_idx[n * KNB + k];
        js[tid] = j;
        dc0[tid] = coords[3*j+0] - coords[3*n+0];
        dc1[tid] = coords[3*j+1] - coords[3*n+1];
        dc2[tid] = coords[3*j+2] - coords[3*n+2];
    }
    w1f[tid] = make_float4(pw1[tid], pw1[CH + tid], pw1[2*CH + tid], pb1[tid]);
    __syncthreads();

    // stage ALL W2 chunks (prepacked image, pure 16B copies)
    for (int it = tid; it < 8192; it += 256) {
        int chunk = it >> 11, rem = it & 2047;
        int k = rem >> 3, q4 = (rem & 7) * 4;
        uint4 v = ((const uint4*)g_w2pack)[it];
        *(uint4*)(sm + OFF_W2 + chunk * W2CHUNK + k * WSTR_B + q4 * 4) = v;
    }
    // H[m][k] = relu(dc . W1col + b1)
    for (int it = tid; it < 128 * 128; it += 256) {
        int m = it >> 7, q = it & 127;
        float4 wa = w1f[2*q], wb = w1f[2*q + 1];
        float d0 = dc0[m], d1 = dc1[m], d2 = dc2[m];
        float h0 = fmaxf(fmaf(d0, wa.x, fmaf(d1, wa.y, fmaf(d2, wa.z, wa.w))), 0.f);
        float h1 = fmaxf(fmaf(d0, wb.x, fmaf(d1, wb.y, fmaf(d2, wb.z, wb.w))), 0.f);
        *(__nv_bfloat162*)(sm + OFF_H + m * HSTR_B + q * 4) = __floats2bfloat162_rn(h0, h1);
    }
    __syncthreads();    // the ONLY barrier — warps are independent below

    const uint32_t sbase = smem_u32(sm);
    const uint32_t aAddrBase = sbase + OFF_H +
        (uint32_t)(wp * 16 + (lane & 15)) * HSTR_B + (uint32_t)(lane >> 4) * 16;

    const int r1 = lane >> 2;
    const int m1 = wp * 16 + r1, m2 = m1 + 8;
    const int j1 = js[m1], j2 = js[m2];
    const float inv = 0.0625f;
    const float* thp = g_theta + (size_t)(n0 + wp) * CH;

#pragma unroll 1
    for (int nc = 0; nc < 4; ++nc) {
        const int nbase = nc * 64;
        const uint32_t bAddrBase = sbase + OFF_W2 + (uint32_t)nc * W2CHUNK
                                 + (uint32_t)(lane & 15) * WSTR_B;

        float acc[8][4];
#pragma unroll
        for (int t = 0; t < 8; ++t)
#pragma unroll
            for (int i = 0; i < 4; ++i) acc[t][i] = 0.f;

#pragma unroll 4
        for (int kt = 0; kt < 16; ++kt) {
            uint32_t a0, a1, a2, a3;
            asm volatile("ldmatrix.sync.aligned.m8n8.x4.shared.b16 {%0,%1,%2,%3}, [%4];"
                         : "=r"(a0), "=r"(a1), "=r"(a2), "=r"(a3)
                         : "r"(aAddrBase + (uint32_t)kt * 32));
#pragma unroll
            for (int t = 0; t < 8; ++t) {
                uint32_t b0, b1;
                asm volatile("ldmatrix.sync.aligned.m8n8.x2.trans.shared.b16 {%0,%1}, [%2];"
                             : "=r"(b0), "=r"(b1)
                             : "r"(bAddrBase + (uint32_t)kt * (16 * WSTR_B) + (uint32_t)t * 16));
                asm volatile("mma.sync.aligned.m16n8k16.row.col.f32.bf16.bf16.f32 "
                             "{%0,%1,%2,%3}, {%4,%5,%6,%7}, {%8,%9}, {%0,%1,%2,%3};"
                             : "+f"(acc[t][0]), "+f"(acc[t][1]), "+f"(acc[t][2]), "+f"(acc[t][3])
                             : "r"(a0), "r"(a1), "r"(a2), "r"(a3), "r"(b0), "r"(b1));
            }
        }

#pragma unroll
        for (int t = 0; t < 8; ++t) {
            int ca = nbase + t * 8 + 2 * (lane & 3);
            float2 th  = *(const float2*)&thp[ca];
            float2 b2  = *(const float2*)&pb2[ca];
            float2 p1  = *(const float2*)&g_phi[(size_t)j1 * CH + ca];
            float2 p2  = *(const float2*)&g_phi[(size_t)j2 * CH + ca];
            float2 gg1 = *(const float2*)&g_gf [(size_t)j1 * CH + ca];
            float2 gg2 = *(const float2*)&g_gf [(size_t)j2 * CH + ca];
            float pe00 = acc[t][0] + b2.x, pe01 = acc[t][1] + b2.y;
            float pe10 = acc[t][2] + b2.x, pe11 = acc[t][3] + b2.y;
            float v00 = fmaf(pe00, th.x - p1.x, pe00) * inv;
            float v01 = fmaf(pe01, th.y - p1.y, pe01) * inv;
            float v10 = fmaf(pe10, th.x - p2.x, pe10) * inv;
            float v11 = fmaf(pe11, th.y - p2.y, pe11) * inv;
            float mx = fmaxf(fmaxf(v00, v01), fmaxf(v10, v11));
#pragma unroll
            for (int off = 4; off <= 16; off <<= 1)
                mx = fmaxf(mx, __shfl_xor_sync(0xffffffffu, mx, off));
            float e00 = __expf(v00 - mx), e01 = __expf(v01 - mx);
            float e10 = __expf(v10 - mx), e11 = __expf(v11 - mx);
            float sa = e00 + e10, sb = e01 + e11;
            float ya = fmaf(e00, gg1.x, e10 * gg2.x);
            float yb = fmaf(e01, gg1.y, e11 * gg2.y);
#pragma unroll
            for (int off = 4; off <= 16; off <<= 1) {
                sa += __shfl_xor_sync(0xffffffffu, sa, off);
                sb += __shfl_xor_sync(0xffffffffu, sb, off);
                ya += __shfl_xor_sync(0xffffffffu, ya, off);
                yb += __shfl_xor_sync(0xffffffffu, yb, off);
            }
            if (lane < 4) {
                uint32_t w0 = splitw(ya / sa);
                uint32_t w1 = splitw(yb / sb);
                *(uint2*)&g_ypack[(size_t)(n0 + wp) * 256 + ca] = make_uint2(w0, w1);
            }
        }
    }
}

// ---------------------------------------------------------------------------
extern "C" void kernel_launch(void* const* d_in, const int* in_sizes, int n_in,
                              void* d_out, int out_size)
{
    const float* coords  = (const float*)d_in[0];
    const float* feats   = (const float*)d_in[1];
    const float* theta_w = (const float*)d_in[2];
    const float* theta_b = (const float*)d_in[3];
    const float* phi_w   = (const float*)d_in[4];
    const float* phi_b   = (const float*)d_in[5];
    const float* g_w     = (const float*)d_in[6];
    const float* g_b     = (const float*)d_in[7];
    const float* pe1_w1  = (const float*)d_in[8];
    const float* pe1_b1  = (const float*)d_in[9];
    const float* pe1_w2  = (const float*)d_in[10];
    const float* pe1_b2  = (const float*)d_in[11];
    const float* W_w     = (const float*)d_in[12];
    const float* W_b     = (const float*)d_in[13];
    float* out = (float*)d_out;

    float *p_theta, *p_phi, *p_g;
    uint32_t *p_ypack, *p_wpack;
    cudaGetSymbolAddress((void**)&p_theta, g_theta);
    cudaGetSymbolAddress((void**)&p_phi,   g_phi);
    cudaGetSymbolAddress((void**)&p_g,     g_gf);
    cudaGetSymbolAddress((void**)&p_ypack, g_ypack);
    cudaGetSymbolAddress((void**)&p_wpack, g_wpack);

    cudaFuncSetAttribute((const void*)attn_kernel,
                         cudaFuncAttributeMaxDynamicSharedMemorySize, ATTN_SMEM);

    grid_count_kernel<<<NPTS / 256, 256>>>(coords);         // 1
    grid_prefix_kernel<<<1, NCELLS>>>();                    // 2
    grid_scatter_kernel<<<NPTS / 256, 256>>>(coords);       // 3
    knn_grid_kernel<<<NPTS / 8, 256>>>(coords);             // 4  <- profiled
    prep_w_kernel<<<2176, 256>>>(pe1_w2, theta_w, phi_w, g_w, W_w);  // 5

    gemmsp_kernel<<<dim3(12, NPTS / 128), 256>>>(           // 6: theta/phi/g
        feats, nullptr, p_wpack, theta_b, phi_b, g_b, p_theta, p_phi, p_g, nullptr);

    attn_kernel<<<NPTS / 8, 256, ATTN_SMEM>>>(coords, pe1_w1, pe1_b1, pe1_b2);  // 7

    gemmsp_kernel<<<dim3(4, NPTS / 128), 256>>>(            // 8: W + residual
        nullptr, p_ypack, p_wpack + (size_t)3 * 2 * 4 * 512 * 32,
        W_b, nullptr, nullptr, out, nullptr, nullptr, feats);
}

// round 14
// speedup vs baseline: 1.1712x; 1.1712x over previous
#include <cuda_runtime.h>
#include <cuda_bf16.h>
#include <cstdint>

#define NPTS 8192
#define CH   256
#define KNB  16

#define GRID   8
#define NCELLS 512
#define CELLSZ 12.5f
#define INVCELL 0.08f

// scratch (device globals: no allocation allowed)
__device__ int   g_idx[NPTS * KNB];
__device__ float g_theta[NPTS * CH];
__device__ float g_phi[NPTS * CH];
__device__ float g_gf[NPTS * CH];
__device__ uint32_t g_w2pack[4 * 8192];        // attn W2, bf16x2 smem image
__device__ uint32_t g_ypack[NPTS * 256];       // y, (hi,lo) bf16 words
__device__ uint32_t g_wpack[4 * 2 * 4 * 512 * 32];  // weights [wsel][plane][nc][512][32]

__device__ int2   g_cellSC[NCELLS];    // (start, count)
__device__ int    g_cellCnt[NCELLS];
__device__ int    g_cellOffs[NCELLS];
__device__ float4 g_spts[NPTS];
__device__ int    g_sidx[NPTS];
__device__ int    g_pcell[NPTS];

__device__ __forceinline__ int cell_of(float x) {
    int c = (int)(x * INVCELL);
    return c < 0 ? 0 : (c > GRID - 1 ? GRID - 1 : c);
}

__device__ __forceinline__ uint32_t smem_u32(const void* p) {
    uint32_t a;
    asm("{ .reg .u64 t; cvta.to.shared.u64 t, %1; cvt.u32.u64 %0, t; }" : "=r"(a) : "l"(p));
    return a;
}

// fp32 -> (bf16 hi | bf16 lo << 16)
__device__ __forceinline__ uint32_t splitw(float v) {
    __nv_bfloat16 h = __float2bfloat16(v);
    float l = v - __bfloat162float(h);
    __nv_bfloat16 lo = __float2bfloat16(l);
    return (uint32_t)__bfloat16_as_ushort(h) | ((uint32_t)__bfloat16_as_ushort(lo) << 16);
}

// ---------------------------------------------------------------------------
// Grid build (g_cellCnt zeroed by grid_prefix after use)
// ---------------------------------------------------------------------------
__global__ void grid_count_kernel(const float* __restrict__ coords) {
    int i = blockIdx.x * 256 + threadIdx.x;
    float x = coords[3*i+0], y = coords[3*i+1], z = coords[3*i+2];
    int c = (cell_of(z) * GRID + cell_of(y)) * GRID + cell_of(x);
    g_pcell[i] = c;
    atomicAdd(&g_cellCnt[c], 1);
}

__global__ void grid_prefix_kernel() {
    __shared__ int tmp[NCELLS];
    int t = threadIdx.x;
    int v = g_cellCnt[t];
    tmp[t] = v;
    __syncthreads();
    for (int off = 1; off < NCELLS; off <<= 1) {
        int a = (t >= off) ? tmp[t - off] : 0;
        __syncthreads();
        tmp[t] += a;
        __syncthreads();
    }
    int excl = tmp[t] - v;
    g_cellSC[t]   = make_int2(excl, v);
    g_cellOffs[t] = excl;
    g_cellCnt[t]  = 0;
}

__global__ void grid_scatter_kernel(const float* __restrict__ coords) {
    int i = blockIdx.x * 256 + threadIdx.x;
    float x = coords[3*i+0], y = coords[3*i+1], z = coords[3*i+2];
    int c = g_pcell[i];
    int pos = atomicAdd(&g_cellOffs[c], 1);
    g_spts[pos] = make_float4(x, y, z, x*x + y*y + z*z);
    g_sidx[pos] = i;
}

// fused weight prepack: attn W2 image + two-plane gemm weights
__global__ void prep_w_kernel(const float* __restrict__ pw2,
                              const float* __restrict__ w0, const float* __restrict__ w1,
                              const float* __restrict__ w2, const float* __restrict__ w3)
{
    int idx = blockIdx.x * 256 + threadIdx.x;
    if (idx < 32768) {
        int nc = idx >> 13, rem = idx & 8191;
        int q = rem & 31, k = rem >> 5;
        const float* p = pw2 + k * CH + nc * 64 + 2 * q;
        ((__nv_bfloat162*)g_w2pack)[idx] = __floats2bfloat162_rn(p[0], p[1]);
        return;
    }
    int i2 = idx - 32768;
    int wsel  = i2 >> 17;
    int plane = (i2 >> 16) & 1;
    int nc    = (i2 >> 14) & 3;
    int row   = (i2 >> 5) & 511;
    int wq    = i2 & 31;
    int k = row >> 1;
    int n = nc * 64 + wq * 2;
    const float* W = wsel == 0 ? w0 : (wsel == 1 ? w1 : (wsel == 2 ? w2 : w3));
    float v0 = W[k * 256 + n], v1 = W[k * 256 + n + 1];
    uint16_t a, b;
    if (plane == 0) {
        a = __bfloat16_as_ushort(__float2bfloat16(v0));
        b = __bfloat16_as_ushort(__float2bfloat16(v1));
    } else {
        a = __bfloat16_as_ushort(__float2bfloat16(v0 - __bfloat162float(__float2bfloat16(v0))));
        b = __bfloat16_as_ushort(__float2bfloat16(v1 - __bfloat162float(__float2bfloat16(v1))));
    }
    g_wpack[i2] = (uint32_t)a | ((uint32_t)b << 16);
}

// ---------------------------------------------------------------------------
// Grid KNN v4: 2 queries/warp (16-lane groups), packed u64 keys,
// adaptive-tau prefilter with exact fallback. (4th launch -> profiled)
// ---------------------------------------------------------------------------
__global__ __launch_bounds__(256) void knn_grid_kernel(const float* __restrict__ coords) {
    const int tid = threadIdx.x;
    const int lg  = tid & 15;
    const unsigned gmask = 0xFFFFu << (tid & 16);
    const int q = blockIdx.x * 16 + (tid >> 4);

    const float qx = coords[3*q+0], qy = coords[3*q+1], qz = coords[3*q+2];
    const float qsq = qx*qx + qy*qy + qz*qz;
    const int cx = cell_of(qx), cy = cell_of(qy), cz = cell_of(qz);
    const int nb = (int)(qx < 11.f || qx > 89.f) + (int)(qy < 11.f || qy > 89.f)
                 + (int)(qz < 11.f || qz > 89.f);
    const float tau0 = nb == 0 ? 120.f : (nb == 1 ? 195.f : (nb == 2 ? 310.f : 490.f));

    bool done = false;
    for (int R = 1; R <= GRID; ++R) {
        if (__all_sync(0xffffffffu, done)) break;
        if (!done) {
            int x0 = max(cx - R, 0), x1 = min(cx + R, GRID - 1);
            int y0 = max(cy - R, 0), y1 = min(cy + R, GRID - 1);
            int z0 = max(cz - R, 0), z1 = min(cz + R, GRID - 1);

            unsigned long long key[KNB];
            float tau = tau0;

            for (int pass = 0; pass < 2; ++pass) {
#pragma unroll
                for (int t = 0; t < KNB; ++t) key[t] = ~0ull;
                int cnt = 0;

                for (int zz = z0; zz <= z1; ++zz)
                for (int yy = y0; yy <= y1; ++yy) {
                    int base = (zz * GRID + yy) * GRID;
                    int2 sA = g_cellSC[base + x0];
                    int2 sB = g_cellSC[base + x1];
                    int en = sB.x + sB.y;          // contiguous x-run
                    for (int i = sA.x + lg; i < en; i += 16) {
                        float4 p = g_spts[i];
                        float dot = fmaf(qx, p.x, fmaf(qy, p.y, qz * p.z));
                        float d = fmaf(-2.f, dot, qsq + p.w);
                        if (d < tau) {
                            ++cnt;
                            unsigned ub = __float_as_uint(d);
                            ub ^= ((unsigned)((int)ub >> 31)) | 0x80000000u;
                            unsigned long long ck =
                                ((unsigned long long)ub << 32) | (unsigned)g_sidx[i];
                            if (ck < key[KNB-1]) {
#pragma unroll
                                for (int t = 0; t < KNB; ++t) {
                                    bool sw = ck < key[t];
                                    unsigned long long tm = sw ? key[t] : ck;
                                    key[t] = sw ? ck : key[t];
                                    ck = tm;
                                }
                            }
                        }
                    }
                }

                int total = cnt;
#pragma unroll
                for (int off = 8; off; off >>= 1)
                    total += __shfl_xor_sync(gmask, total, off);
                if (total >= KNB) break;   // filtered set provably contains top-16
                tau = 3.4e38f;             // rare: rescan without filter
            }

            // group merge: 16 rounds of 16-lane min-reduce over sorted heads
            unsigned long long head = key[0];
            unsigned long long m = ~0ull;
            for (int k = 0; k < KNB; ++k) {
                m = head;
#pragma unroll
                for (int off = 8; off; off >>= 1) {
                    unsigned long long o = __shfl_xor_sync(gmask, m, off);
                    if (o < m) m = o;
                }
                if (lg == 0) g_idx[q * KNB + k] = (int)(unsigned)m;
                if (head == m) {
#pragma unroll
                    for (int t = 0; t < KNB-1; ++t) key[t] = key[t+1];
                    key[KNB-1] = ~0ull;
                    head = key[0];
                }
            }

            unsigned ue = (unsigned)(m >> 32);
            ue ^= (ue & 0x80000000u) ? 0x80000000u : 0xFFFFFFFFu;
            float r16 = __uint_as_float(ue);

            float bmin = 1e30f;
            if (x0 > 0)        bmin = fminf(bmin, qx - (float)x0 * CELLSZ);
            if (x1 < GRID - 1) bmin = fminf(bmin, (float)(x1 + 1) * CELLSZ - qx);
            if (y0 > 0)        bmin = fminf(bmin, qy - (float)y0 * CELLSZ);
            if (y1 < GRID - 1) bmin = fminf(bmin, (float)(y1 + 1) * CELLSZ - qy);
            if (z0 > 0)        bmin = fminf(bmin, qz - (float)z0 * CELLSZ);
            if (z1 < GRID - 1) bmin = fminf(bmin, (float)(z1 + 1) * CELLSZ - qz);
            if (r16 <= bmin * bmin - 0.5f) done = true;
        }
    }
}

// ---------------------------------------------------------------------------
// Split-bf16 tensor GEMM. A either fp32 (split on the fly) or prepacked words.
// ---------------------------------------------------------------------------
#define GSTR 36   // words per smem row (72 bf16 = 144B)

__global__ __launch_bounds__(256) void gemmsp_kernel(
    const float* __restrict__ Af, const uint32_t* __restrict__ Ap,
    const uint32_t* __restrict__ Bp,
    const float* __restrict__ bias0, const float* __restrict__ bias1,
    const float* __restrict__ bias2,
    float* __restrict__ out0, float* __restrict__ out1, float* __restrict__ out2,
    const float* __restrict__ resid)
{
    __shared__ __align__(16) uint32_t As[128 * GSTR];
    __shared__ __align__(16) uint32_t Bs[64 * GSTR];

    const int tid = threadIdx.x, lane = tid & 31, w = tid >> 5;
    const int wm = w & 3, wn = w >> 2;
    const int m0 = blockIdx.y * 128;
    const int nc = blockIdx.x & 3;
    const int wsel = blockIdx.x >> 2;
    const float* bias = wsel == 0 ? bias0 : (wsel == 1 ? bias1 : bias2);
    float* outp = wsel == 0 ? out0 : (wsel == 1 ? out1 : out2);

    float acc[2][4][4];
#pragma unroll
    for (int t = 0; t < 2; ++t)
#pragma unroll
        for (int u = 0; u < 4; ++u)
#pragma unroll
            for (int i = 0; i < 4; ++i) acc[t][u][i] = 0.f;

    uint4 aR[4], bR[2];
    const int arow4 = tid >> 3, awq = (tid & 7) * 4;

#define LD_A(c) { \
    if (Af) { \
        _Pragma("unroll") \
        for (int u2 = 0; u2 < 4; ++u2) { \
            float4 f = *(const float4*)&Af[(size_t)(m0 + arow4 + u2 * 32) * 256 + (c) * 32 + awq]; \
            aR[u2].x = splitw(f.x); aR[u2].y = splitw(f.y); \
            aR[u2].z = splitw(f.z); aR[u2].w = splitw(f.w); \
        } \
    } else { \
        _Pragma("unroll") \
        for (int u2 = 0; u2 < 4; ++u2) \
            aR[u2] = *(const uint4*)&Ap[(size_t)(m0 + arow4 + u2 * 32) * 256 + (c) * 32 + awq]; \
    } }
#define LD_B(c, pl) { \
    _Pragma("unroll") \
    for (int u2 = 0; u2 < 2; ++u2) \
        bR[u2] = *(const uint4*)&Bp[((((size_t)wsel * 2 + (pl)) * 4 + nc) * 512 + (size_t)(c) * 64 + arow4 + u2 * 32) * 32 + awq]; }

    LD_A(0); LD_B(0, 0);

    const uint32_t smA = smem_u32(As), smB = smem_u32(Bs);
    const uint32_t aBase = smA + (uint32_t)((wm * 32 + (lane & 15)) * 144 + (lane >> 4) * 16);
    const uint32_t bBase = smB + (uint32_t)((lane & 15) * 144 + wn * 64);

    for (int s = 0; s < 16; ++s) {
        const int plane = s & 1;
        __syncthreads();
        if (plane == 0) {
#pragma unroll
            for (int u2 = 0; u2 < 4; ++u2)
                *(uint4*)&As[(arow4 + u2 * 32) * GSTR + awq] = aR[u2];
        }
#pragma unroll
        for (int u2 = 0; u2 < 2; ++u2)
            *(uint4*)&Bs[(arow4 + u2 * 32) * GSTR + awq] = bR[u2];
        __syncthreads();

        if (s < 15) {
            const int c2 = (s + 1) >> 1, p2 = (s + 1) & 1;
            if (p2 == 0) LD_A(c2);
            LD_B(c2, p2);
        }

#pragma unroll
        for (int ks = 0; ks < 4; ++ks) {
            uint32_t a[2][4];
#pragma unroll
            for (int t = 0; t < 2; ++t)
                asm volatile("ldmatrix.sync.aligned.m8n8.x4.shared.b16 {%0,%1,%2,%3}, [%4];"
                             : "=r"(a[t][0]), "=r"(a[t][1]), "=r"(a[t][2]), "=r"(a[t][3])
                             : "r"(aBase + (uint32_t)(t * 16 * 144 + ks * 32)));
#pragma unroll
            for (int u = 0; u < 4; ++u) {
                uint32_t b0, b1;
                asm volatile("ldmatrix.sync.aligned.m8n8.x2.trans.shared.b16 {%0,%1}, [%2];"
                             : "=r"(b0), "=r"(b1)
                             : "r"(bBase + (uint32_t)(ks * 16 * 144 + u * 16)));
#pragma unroll
                for (int t = 0; t < 2; ++t)
                    asm volatile("mma.sync.aligned.m16n8k16.row.col.f32.bf16.bf16.f32 "
                                 "{%0,%1,%2,%3}, {%4,%5,%6,%7}, {%8,%9}, {%0,%1,%2,%3};"
                                 : "+f"(acc[t][u][0]), "+f"(acc[t][u][1]),
                                   "+f"(acc[t][u][2]), "+f"(acc[t][u][3])
                                 : "r"(a[t][0]), "r"(a[t][1]), "r"(a[t][2]), "r"(a[t][3]),
                                   "r"(b0), "r"(b1));
            }
        }
    }

#pragma unroll
    for (int t = 0; t < 2; ++t) {
        int r0 = m0 + wm * 32 + t * 16 + (lane >> 2);
#pragma unroll
        for (int u = 0; u < 4; ++u) {
            int nb = nc * 64 + wn * 32 + u * 8 + 2 * (lane & 3);
            float2 b = *(const float2*)&bias[nb];
            float2 o0 = make_float2(acc[t][u][0] + b.x, acc[t][u][1] + b.y);
            float2 o1 = make_float2(acc[t][u][2] + b.x, acc[t][u][3] + b.y);
            if (resid) {
                float2 ra = *(const float2*)&resid[(size_t)r0 * 256 + nb];
                float2 rb = *(const float2*)&resid[(size_t)(r0 + 8) * 256 + nb];
                o0.x += ra.x; o0.y += ra.y; o1.x += rb.x; o1.y += rb.y;
            }
            *(float2*)&outp[(size_t)r0 * 256 + nb]       = o0;
            *(float2*)&outp[(size_t)(r0 + 8) * 256 + nb] = o1;
        }
    }
}

// ===========================================================================
// Fused attention (HMMA) — R7 configuration (best measured): 8 points,
// 256 threads, occupancy 2, per-chunk W2 staging from prepacked image.
// ===========================================================================
#define OFF_JS   0
#define OFF_DC   512
#define OFF_W1   2048
#define OFF_H    6144
#define HSTR_B   528
#define OFF_W2   73728
#define WSTR_B   144
#define ATTN_SMEM 110592

__global__ __launch_bounds__(256, 2) void attn_kernel(
    const float* __restrict__ coords,
    const float* __restrict__ pw1, const float* __restrict__ pb1,
    const float* __restrict__ pb2)
{
    extern __shared__ __align__(16) char sm[];
    int*    js  = (int*)(sm + OFF_JS);
    float*  dc0 = (float*)(sm + OFF_DC);
    float*  dc1 = dc0 + 128;
    float*  dc2 = dc0 + 256;
    float4* w1f = (float4*)(sm + OFF_W1);

    const int tid  = threadIdx.x;
    const int lane = tid & 31;
    const int wp   = tid >> 5;
    const int n0   = blockIdx.x * 8;

    if (tid < 128) {
        int p = tid >> 4, k = tid & 15;
        int n = n0 + p;
        int j = g_idx[n * KNB + k];
        js[tid] = j;
        dc0[tid] = coords[3*j+0] - coords[3*n+0];
        dc1[tid] = coords[3*j+1] - coords[3*n+1];
        dc2[tid] = coords[3*j+2] - coords[3*n+2];
    }
    w1f[tid] = make_float4(pw1[tid], pw1[CH + tid], pw1[2*CH + tid], pb1[tid]);
    __syncthreads();

    for (int it = tid; it < 128 * 128; it += 256) {
        int m = it >> 7, q = it & 127;
        float4 wa = w1f[2*q], wb = w1f[2*q + 1];
        float d0 = dc0[m], d1 = dc1[m], d2 = dc2[m];
        float h0 = fmaxf(fmaf(d0, wa.x, fmaf(d1, wa.y, fmaf(d2, wa.z, wa.w))), 0.f);
        float h1 = fmaxf(fmaf(d0, wb.x, fmaf(d1, wb.y, fmaf(d2, wb.z, wb.w))), 0.f);
        *(__nv_bfloat162*)(sm + OFF_H + m * HSTR_B + q * 4) = __floats2bfloat162_rn(h0, h1);
    }

    const uint32_t sbase = smem_u32(sm);
    const uint32_t aAddrBase = sbase + OFF_H +
        (uint32_t)(wp * 16 + (lane & 15)) * HSTR_B + (uint32_t)(lane >> 4) * 16;
    const uint32_t bAddrBase = sbase + OFF_W2 + (uint32_t)(lane & 15) * WSTR_B;

    const int r1 = lane >> 2;
    const int m1 = wp * 16 + r1, m2 = m1 + 8;
    const float inv = 0.0625f;

    for (int nc = 0; nc < 4; ++nc) {
        const int nbase = nc * 64;
        __syncthreads();
        for (int it = tid; it < 2048; it += 256) {
            int k = it >> 3, q4 = (it & 7) * 4;
            uint4 v = ((const uint4*)g_w2pack)[nc * 2048 + it];
            *(uint4*)(sm + OFF_W2 + k * WSTR_B + q4 * 4) = v;
        }
        __syncthreads();

        float acc[8][4];
#pragma unroll
        for (int t = 0; t < 8; ++t)
#pragma unroll
            for (int i = 0; i < 4; ++i) acc[t][i] = 0.f;

#pragma unroll 4
        for (int kt = 0; kt < 16; ++kt) {
            uint32_t a0, a1, a2, a3;
            asm volatile("ldmatrix.sync.aligned.m8n8.x4.shared.b16 {%0,%1,%2,%3}, [%4];"
                         : "=r"(a0), "=r"(a1), "=r"(a2), "=r"(a3)
                         : "r"(aAddrBase + (uint32_t)kt * 32));
#pragma unroll
            for (int t = 0; t < 8; ++t) {
                uint32_t b0, b1;
                asm volatile("ldmatrix.sync.aligned.m8n8.x2.trans.shared.b16 {%0,%1}, [%2];"
                             : "=r"(b0), "=r"(b1)
                             : "r"(bAddrBase + (uint32_t)kt * (16 * WSTR_B) + (uint32_t)t * 16));
                asm volatile("mma.sync.aligned.m16n8k16.row.col.f32.bf16.bf16.f32 "
                             "{%0,%1,%2,%3}, {%4,%5,%6,%7}, {%8,%9}, {%0,%1,%2,%3};"
                             : "+f"(acc[t][0]), "+f"(acc[t][1]), "+f"(acc[t][2]), "+f"(acc[t][3])
                             : "r"(a0), "r"(a1), "r"(a2), "r"(a3), "r"(b0), "r"(b1));
            }
        }

        const int j1 = js[m1], j2 = js[m2];
        const float* thp = g_theta + (size_t)(n0 + wp) * CH;
#pragma unroll
        for (int t = 0; t < 8; ++t) {
            int ca = nbase + t * 8 + 2 * (lane & 3);
            float2 th  = *(const float2*)&thp[ca];
            float2 b2  = *(const float2*)&pb2[ca];
            float2 p1  = *(const float2*)&g_phi[(size_t)j1 * CH + ca];
            float2 p2  = *(const float2*)&g_phi[(size_t)j2 * CH + ca];
            float2 gg1 = *(const float2*)&g_gf [(size_t)j1 * CH + ca];
            float2 gg2 = *(const float2*)&g_gf [(size_t)j2 * CH + ca];
            float pe00 = acc[t][0] + b2.x, pe01 = acc[t][1] + b2.y;
            float pe10 = acc[t][2] + b2.x, pe11 = acc[t][3] + b2.y;
            float v00 = fmaf(pe00, th.x - p1.x, pe00) * inv;
            float v01 = fmaf(pe01, th.y - p1.y, pe01) * inv;
            float v10 = fmaf(pe10, th.x - p2.x, pe10) * inv;
            float v11 = fmaf(pe11, th.y - p2.y, pe11) * inv;
            float mx = fmaxf(fmaxf(v00, v01), fmaxf(v10, v11));
#pragma unroll
            for (int off = 4; off <= 16; off <<= 1)
                mx = fmaxf(mx, __shfl_xor_sync(0xffffffffu, mx, off));
            float e00 = __expf(v00 - mx), e01 = __expf(v01 - mx);
            float e10 = __expf(v10 - mx), e11 = __expf(v11 - mx);
            float sa = e00 + e10, sb = e01 + e11;
            float ya = fmaf(e00, gg1.x, e10 * gg2.x);
            float yb = fmaf(e01, gg1.y, e11 * gg2.y);
#pragma unroll
            for (int off = 4; off <= 16; off <<= 1) {
                sa += __shfl_xor_sync(0xffffffffu, sa, off);
                sb += __shfl_xor_sync(0xffffffffu, sb, off);
                ya += __shfl_xor_sync(0xffffffffu, ya, off);
                yb += __shfl_xor_sync(0xffffffffu, yb, off);
            }
            if (lane < 4) {
                uint32_t w0 = splitw(ya / sa);
                uint32_t w1 = splitw(yb / sb);
                *(uint2*)&g_ypack[(size_t)(n0 + wp) * 256 + ca] = make_uint2(w0, w1);
            }
        }
    }
}

// ---------------------------------------------------------------------------
extern "C" void kernel_launch(void* const* d_in, const int* in_sizes, int n_in,
                              void* d_out, int out_size)
{
    const float* coords  = (const float*)d_in[0];
    const float* feats   = (const float*)d_in[1];
    const float* theta_w = (const float*)d_in[2];
    const float* theta_b = (const float*)d_in[3];
    const float* phi_w   = (const float*)d_in[4];
    const float* phi_b   = (const float*)d_in[5];
    const float* g_w     = (const float*)d_in[6];
    const float* g_b     = (const float*)d_in[7];
    const float* pe1_w1  = (const float*)d_in[8];
    const float* pe1_b1  = (const float*)d_in[9];
    const float* pe1_w2  = (const float*)d_in[10];
    const float* pe1_b2  = (const float*)d_in[11];
    const float* W_w     = (const float*)d_in[12];
    const float* W_b     = (const float*)d_in[13];
    float* out = (float*)d_out;

    float *p_theta, *p_phi, *p_g;
    uint32_t *p_ypack, *p_wpack;
    cudaGetSymbolAddress((void**)&p_theta, g_theta);
    cudaGetSymbolAddress((void**)&p_phi,   g_phi);
    cudaGetSymbolAddress((void**)&p_g,     g_gf);
    cudaGetSymbolAddress((void**)&p_ypack, g_ypack);
    cudaGetSymbolAddress((void**)&p_wpack, g_wpack);

    cudaFuncSetAttribute((const void*)attn_kernel,
                         cudaFuncAttributeMaxDynamicSharedMemorySize, ATTN_SMEM);

    grid_count_kernel<<<NPTS / 256, 256>>>(coords);         // 1
    grid_prefix_kernel<<<1, NCELLS>>>();                    // 2
    grid_scatter_kernel<<<NPTS / 256, 256>>>(coords);       // 3
    knn_grid_kernel<<<NPTS / 16, 256>>>(coords);            // 4  <- profiled
    prep_w_kernel<<<2176, 256>>>(pe1_w2, theta_w, phi_w, g_w, W_w);  // 5

    gemmsp_kernel<<<dim3(12, NPTS / 128), 256>>>(           // 6: theta/phi/g
        feats, nullptr, p_wpack, theta_b, phi_b, g_b, p_theta, p_phi, p_g, nullptr);

    attn_kernel<<<NPTS / 8, 256, ATTN_SMEM>>>(coords, pe1_w1, pe1_b1, pe1_b2);  // 7

    gemmsp_kernel<<<dim3(4, NPTS / 128), 256>>>(            // 8: W + residual
        nullptr, p_ypack, p_wpack + (size_t)3 * 2 * 4 * 512 * 32,
        W_b, nullptr, nullptr, out, nullptr, nullptr, feats);
}